// round 6
// baseline (speedup 1.0000x reference)
#include <cuda_runtime.h>
#include <cstdint>

#define SIGMA_INV 10000.0f  // 1 / 1e-4

// factor = 1 - prob = 1 - sigmoid(-d/sigma)*mask = mask ? sigmoid(d/sigma) : 1
__device__ __forceinline__ float blend_factor(float d, int face) {
    float s = __fdividef(1.0f, 1.0f + __expf(-d * SIGMA_INV));
    return (face >= 0) ? s : 1.0f;
}

// Warp-cooperative: each warp handles 32 pixels. Thread loads float4/int4 at
// index warp_base*128 + lane + 32*j  (j=0..3) -> every LDG.128 is a fully
// contiguous 512B warp transaction. For fixed j, lanes 4g..4g+3 hold the 4
// K-quarters of pixel base + g + 8*j.
__global__ void __launch_bounds__(256)
self_shader_kernel(const float* __restrict__ zbuf,
                   const float* __restrict__ dists,
                   const int* __restrict__ pix_to_face,
                   float* __restrict__ out,
                   int n_pix) {
    int gtid   = blockIdx.x * blockDim.x + threadIdx.x;
    int warpid = gtid >> 5;
    int lane   = gtid & 31;

    size_t base_pix = (size_t)warpid * 32;
    if (base_pix >= (size_t)n_pix) return;

    const float4* d4 = reinterpret_cast<const float4*>(dists);
    const int4*   f4 = reinterpret_cast<const int4*>(pix_to_face);
    size_t base_f4 = base_pix << 2;   // 4 float4 per pixel

    // Front-batched, perfectly coalesced streaming loads (8x LDG.128)
    float4 d0 = __ldcs(d4 + base_f4 + lane);
    float4 d1 = __ldcs(d4 + base_f4 + lane + 32);
    float4 d2 = __ldcs(d4 + base_f4 + lane + 64);
    float4 d3 = __ldcs(d4 + base_f4 + lane + 96);
    int4   f0 = __ldcs(f4 + base_f4 + lane);
    int4   f1 = __ldcs(f4 + base_f4 + lane + 32);
    int4   f2 = __ldcs(f4 + base_f4 + lane + 64);
    int4   f3 = __ldcs(f4 + base_f4 + lane + 96);

    float p0 = blend_factor(d0.x, f0.x) * blend_factor(d0.y, f0.y)
             * blend_factor(d0.z, f0.z) * blend_factor(d0.w, f0.w);
    float p1 = blend_factor(d1.x, f1.x) * blend_factor(d1.y, f1.y)
             * blend_factor(d1.z, f1.z) * blend_factor(d1.w, f1.w);
    float p2 = blend_factor(d2.x, f2.x) * blend_factor(d2.y, f2.y)
             * blend_factor(d2.z, f2.z) * blend_factor(d2.w, f2.w);
    float p3 = blend_factor(d3.x, f3.x) * blend_factor(d3.y, f3.y)
             * blend_factor(d3.z, f3.z) * blend_factor(d3.w, f3.w);

    // reduce across each 4-lane group (one pixel per group per j)
    p0 *= __shfl_xor_sync(0xFFFFFFFFu, p0, 1);
    p0 *= __shfl_xor_sync(0xFFFFFFFFu, p0, 2);
    p1 *= __shfl_xor_sync(0xFFFFFFFFu, p1, 1);
    p1 *= __shfl_xor_sync(0xFFFFFFFFu, p1, 2);
    p2 *= __shfl_xor_sync(0xFFFFFFFFu, p2, 1);
    p2 *= __shfl_xor_sync(0xFFFFFFFFu, p2, 2);
    p3 *= __shfl_xor_sync(0xFFFFFFFFu, p3, 1);
    p3 *= __shfl_xor_sync(0xFFFFFFFFu, p3, 2);

    if ((lane & 3) == 0) {
        int g = lane >> 2;                       // 0..7
        size_t px0 = base_pix + g;               // + 8*j for j=0..3
        // zbuf channel 0 only (64B stride; 2 pixels share a 128B line)
        float z0 = __ldg(&zbuf[(px0      ) << 4]);
        float z1 = __ldg(&zbuf[(px0 +  8 ) << 4]);
        float z2 = __ldg(&zbuf[(px0 + 16 ) << 4]);
        float z3 = __ldg(&zbuf[(px0 + 24 ) << 4]);
        float4* o4 = reinterpret_cast<float4*>(out);
        // 8 writer lanes x contiguous pixels -> one full 128B line per STG
        __stcs(o4 + px0,      make_float4(z0, z0, z0, 1.0f - p0));
        __stcs(o4 + px0 +  8, make_float4(z1, z1, z1, 1.0f - p1));
        __stcs(o4 + px0 + 16, make_float4(z2, z2, z2, 1.0f - p2));
        __stcs(o4 + px0 + 24, make_float4(z3, z3, z3, 1.0f - p3));
    }
}

extern "C" void kernel_launch(void* const* d_in, const int* in_sizes, int n_in,
                              void* d_out, int out_size) {
    const float* zbuf  = (const float*)d_in[0];
    const float* dists = (const float*)d_in[1];
    const int*   p2f   = (const int*)d_in[2];
    float*       out   = (float*)d_out;

    int n_pix = in_sizes[0] / 16;   // N*H*W
    // one warp per 32 pixels
    long long warps = ((long long)n_pix + 31) / 32;
    long long threads_total = warps * 32;
    int block = 256;
    int grid = (int)((threads_total + block - 1) / block);

    self_shader_kernel<<<grid, block>>>(zbuf, dists, p2f, out, n_pix);
}